// round 4
// baseline (speedup 1.0000x reference)
#include <cuda_runtime.h>

#define BB   8
#define CC   256
#define CID  64
#define NN   4096
#define LOG2E 1.4426950408889634f

// Scratch (no allocations allowed): 4 x 8MB + 64KB
__device__ float d_theta[BB * NN * CID];  // [b][n][k], pre-scaled by log2(e)
__device__ float d_phi  [BB * CID * NN];  // [b][k][n]
__device__ float d_gm   [BB * NN * CID];  // [b][n][k]
__device__ float d_y    [BB * NN * CID];  // [b][n][k]
__device__ float d_wT   [CID * CC];       // [k][c]

__device__ __forceinline__ float ex2f(float x) {
    float y; asm("ex2.approx.f32 %0, %1;" : "=f"(y) : "f"(x)); return y;
}

// XOR swizzle on the column index so that rows r and r+4 (the two ty-groups of
// a warp doing scalar broadcast reads at the same k) land in different banks.
#define SWZ(r, c) ((c) ^ ((r) & 28))

#define FMA16(A, a0, a1, a2, a3, bv)                                             \
    A[0][0] += (a0) * bv.x; A[0][1] += (a0) * bv.y; A[0][2] += (a0) * bv.z; A[0][3] += (a0) * bv.w; \
    A[1][0] += (a1) * bv.x; A[1][1] += (a1) * bv.y; A[1][2] += (a1) * bv.z; A[1][3] += (a1) * bv.w; \
    A[2][0] += (a2) * bv.x; A[2][1] += (a2) * bv.y; A[2][2] += (a2) * bv.z; A[2][3] += (a2) * bv.w; \
    A[3][0] += (a3) * bv.x; A[3][1] += (a3) * bv.y; A[3][2] += (a3) * bv.z; A[3][3] += (a3) * bv.w;

// ---------------------------------------------------------------------------
// Kernel 1: 1x1-conv projections. grid (N/64, B, 3), 256 threads.
// z=0: theta (scaled by log2e) -> [b][n][k]
// z=1: phi                     -> [b][k][n]
// z=2: g                       -> [b][n][k]
// ---------------------------------------------------------------------------
__global__ __launch_bounds__(256)
void proj_kernel(const float* __restrict__ x,
                 const float* __restrict__ gw, const float* __restrict__ gb,
                 const float* __restrict__ tw, const float* __restrict__ tb,
                 const float* __restrict__ pw, const float* __restrict__ pb)
{
    __shared__ float xs[64][64];   // [k][n]  (vector reads, same-row -> no pad)
    __shared__ float ws[64][64];   // [ci][k] (scalar broadcast reads -> swizzled)

    const int tid = threadIdx.x;
    const int tx = tid & 15, ty = tid >> 4;
    const int n0 = blockIdx.x * 64;
    const int b  = blockIdx.y;
    const int pr = blockIdx.z;
    const float* w  = (pr == 0) ? tw : (pr == 1) ? pw : gw;
    const float* bi = (pr == 0) ? tb : (pr == 1) ? pb : gb;

    float acc[4][4] = {};

    for (int kc = 0; kc < CC; kc += 64) {
        #pragma unroll
        for (int rr = 0; rr < 64; rr += 16) {
            const int r  = rr + ty;
            const int c4 = tx * 4;
            *(float4*)&xs[r][c4] =
                *(const float4*)&x[((size_t)(b * CC + kc + r)) * NN + n0 + c4];
            *(float4*)&ws[r][SWZ(r, c4)] =
                *(const float4*)&w[(size_t)r * CC + kc + c4];
        }
        __syncthreads();
        #pragma unroll 8
        for (int k = 0; k < 64; k++) {
            const float4 bv = *(const float4*)&xs[k][tx * 4];
            const float a0 = ws[ty * 4 + 0][SWZ(ty * 4 + 0, k)];
            const float a1 = ws[ty * 4 + 1][SWZ(ty * 4 + 1, k)];
            const float a2 = ws[ty * 4 + 2][SWZ(ty * 4 + 2, k)];
            const float a3 = ws[ty * 4 + 3][SWZ(ty * 4 + 3, k)];
            FMA16(acc, a0, a1, a2, a3, bv);
        }
        __syncthreads();
    }

    if (pr == 1) {
        // phi: [b][ci][n] — per i, float4 over n
        #pragma unroll
        for (int i = 0; i < 4; i++) {
            const int ci = ty * 4 + i;
            const float bb_ = bi[ci];
            float4 v = make_float4(acc[i][0] + bb_, acc[i][1] + bb_,
                                   acc[i][2] + bb_, acc[i][3] + bb_);
            *(float4*)&d_phi[((size_t)(b * CID + ci)) * NN + n0 + tx * 4] = v;
        }
    } else {
        float* outb = (pr == 0) ? d_theta : d_gm;
        const float sc = (pr == 0) ? LOG2E : 1.0f;
        const float b0 = bi[ty * 4 + 0], b1 = bi[ty * 4 + 1];
        const float b2 = bi[ty * 4 + 2], b3 = bi[ty * 4 + 3];
        #pragma unroll
        for (int j = 0; j < 4; j++) {
            const int n = n0 + tx * 4 + j;
            float4 v = make_float4((acc[0][j] + b0) * sc, (acc[1][j] + b1) * sc,
                                   (acc[2][j] + b2) * sc, (acc[3][j] + b3) * sc);
            *(float4*)&outb[((size_t)(b * NN + n)) * CID + ty * 4] = v;
        }
    }
}

// ---------------------------------------------------------------------------
// Kernel 2: transpose w_w [C][CI] -> d_wT [CI][C]
// ---------------------------------------------------------------------------
__global__ __launch_bounds__(256)
void wtrans_kernel(const float* __restrict__ ww)
{
    const int idx = blockIdx.x * 256 + threadIdx.x;  // 16384 total
    const int c = idx >> 6, k = idx & 63;
    d_wT[k * CC + c] = ww[idx];
}

// ---------------------------------------------------------------------------
// Kernel 3: flash attention. grid (N/64, B), 256 threads, 48KB static smem.
// Block handles 64 query rows; loops over 64 key/value tiles of 64.
// ---------------------------------------------------------------------------
__global__ __launch_bounds__(256)
void attn_kernel()
{
    __shared__ float th_s[64][64];  // theta [r][k]   (scalar reads, swizzled)
    __shared__ float pp_s[64][64];  // phi [k][c], then P [r][c] (P swizzled)
    __shared__ float g_s [64][64];  // g [c][ci]      (vector reads)

    const int tid = threadIdx.x;
    const int tx = tid & 15, ty = tid >> 4;
    const int b  = blockIdx.y;
    const int r0 = blockIdx.x * 64;

    #pragma unroll
    for (int rr = 0; rr < 64; rr += 16) {
        const int r = rr + ty, c4 = tx * 4;
        *(float4*)&th_s[r][SWZ(r, c4)] =
            *(const float4*)&d_theta[((size_t)(b * NN + r0 + r)) * CID + c4];
    }

    float m_i[4], l_i[4], o[4][4] = {};
    #pragma unroll
    for (int i = 0; i < 4; i++) { m_i[i] = -1e30f; l_i[i] = 0.0f; }
    __syncthreads();

    for (int jt = 0; jt < 64; jt++) {
        const int c0 = jt * 64;
        #pragma unroll
        for (int rr = 0; rr < 64; rr += 16) {
            const int r = rr + ty, c4 = tx * 4;
            *(float4*)&pp_s[r][c4] =
                *(const float4*)&d_phi[((size_t)(b * CID + r)) * NN + c0 + c4];
            *(float4*)&g_s[r][c4] =
                *(const float4*)&d_gm[((size_t)(b * NN + c0 + r)) * CID + c4];
        }
        __syncthreads();

        // S = theta @ phi  (scores already in log2 domain: theta pre-scaled)
        float s[4][4] = {};
        #pragma unroll 8
        for (int k = 0; k < 64; k++) {
            const float4 bv = *(const float4*)&pp_s[k][tx * 4];
            const float a0 = th_s[ty * 4 + 0][SWZ(ty * 4 + 0, k)];
            const float a1 = th_s[ty * 4 + 1][SWZ(ty * 4 + 1, k)];
            const float a2 = th_s[ty * 4 + 2][SWZ(ty * 4 + 2, k)];
            const float a3 = th_s[ty * 4 + 3][SWZ(ty * 4 + 3, k)];
            FMA16(s, a0, a1, a2, a3, bv);
        }
        __syncthreads();  // all threads done reading phi; pp_s reusable for P

        // Online softmax update per row (row reduce across the 16 tx lanes)
        #pragma unroll
        for (int i = 0; i < 4; i++) {
            const int r = ty * 4 + i;
            float mx = fmaxf(fmaxf(s[i][0], s[i][1]), fmaxf(s[i][2], s[i][3]));
            mx = fmaxf(mx, __shfl_xor_sync(0xffffffffu, mx, 1));
            mx = fmaxf(mx, __shfl_xor_sync(0xffffffffu, mx, 2));
            mx = fmaxf(mx, __shfl_xor_sync(0xffffffffu, mx, 4));
            mx = fmaxf(mx, __shfl_xor_sync(0xffffffffu, mx, 8));
            const float mnew = fmaxf(m_i[i], mx);
            const float p0 = ex2f(s[i][0] - mnew);
            const float p1 = ex2f(s[i][1] - mnew);
            const float p2 = ex2f(s[i][2] - mnew);
            const float p3 = ex2f(s[i][3] - mnew);
            float rs = p0 + p1 + p2 + p3;
            rs += __shfl_xor_sync(0xffffffffu, rs, 1);
            rs += __shfl_xor_sync(0xffffffffu, rs, 2);
            rs += __shfl_xor_sync(0xffffffffu, rs, 4);
            rs += __shfl_xor_sync(0xffffffffu, rs, 8);
            const float sc = ex2f(m_i[i] - mnew);
            l_i[i] = l_i[i] * sc + rs;
            m_i[i] = mnew;
            o[i][0] *= sc; o[i][1] *= sc; o[i][2] *= sc; o[i][3] *= sc;
            *(float4*)&pp_s[r][SWZ(r, tx * 4)] = make_float4(p0, p1, p2, p3);
        }
        __syncthreads();  // P visible to all threads

        // O += P @ g
        #pragma unroll 8
        for (int k = 0; k < 64; k++) {
            const float4 gv = *(const float4*)&g_s[k][tx * 4];
            const float a0 = pp_s[ty * 4 + 0][SWZ(ty * 4 + 0, k)];
            const float a1 = pp_s[ty * 4 + 1][SWZ(ty * 4 + 1, k)];
            const float a2 = pp_s[ty * 4 + 2][SWZ(ty * 4 + 2, k)];
            const float a3 = pp_s[ty * 4 + 3][SWZ(ty * 4 + 3, k)];
            FMA16(o, a0, a1, a2, a3, gv);
        }
        __syncthreads();  // safe to overwrite pp_s / g_s next tile
    }

    #pragma unroll
    for (int i = 0; i < 4; i++) {
        const float inv = 1.0f / l_i[i];
        float4 v = make_float4(o[i][0] * inv, o[i][1] * inv,
                               o[i][2] * inv, o[i][3] * inv);
        *(float4*)&d_y[((size_t)(b * NN + r0 + ty * 4 + i)) * CID + tx * 4] = v;
    }
}

// ---------------------------------------------------------------------------
// Kernel 4: out = w_w @ y + w_b + x. grid (N/64, C/64, B), 256 threads.
// acc[i][j]: n = n0 + ty*4+i, c = c0 + tx*4+j
// ---------------------------------------------------------------------------
__global__ __launch_bounds__(256)
void out_kernel(const float* __restrict__ x, const float* __restrict__ wb,
                float* __restrict__ out)
{
    __shared__ float y_s [64][64];  // [n][k] (scalar reads, swizzled)
    __shared__ float wT_s[64][64];  // [k][c] (vector reads)

    const int tid = threadIdx.x;
    const int tx = tid & 15, ty = tid >> 4;
    const int n0 = blockIdx.x * 64;
    const int c0 = blockIdx.y * 64;
    const int b  = blockIdx.z;

    #pragma unroll
    for (int rr = 0; rr < 64; rr += 16) {
        const int r = rr + ty, c4 = tx * 4;
        *(float4*)&y_s[r][SWZ(r, c4)] =
            *(const float4*)&d_y[((size_t)(b * NN + n0 + r)) * CID + c4];
        *(float4*)&wT_s[r][c4] = *(const float4*)&d_wT[r * CC + c0 + c4];
    }
    __syncthreads();

    float acc[4][4] = {};
    #pragma unroll 8
    for (int k = 0; k < 64; k++) {
        const float4 bv = *(const float4*)&wT_s[k][tx * 4];
        const float a0 = y_s[ty * 4 + 0][SWZ(ty * 4 + 0, k)];
        const float a1 = y_s[ty * 4 + 1][SWZ(ty * 4 + 1, k)];
        const float a2 = y_s[ty * 4 + 2][SWZ(ty * 4 + 2, k)];
        const float a3 = y_s[ty * 4 + 3][SWZ(ty * 4 + 3, k)];
        FMA16(acc, a0, a1, a2, a3, bv);
    }

    #pragma unroll
    for (int j = 0; j < 4; j++) {
        const int c = c0 + tx * 4 + j;
        const float wbc = wb[c];
        const size_t base = ((size_t)(b * CC + c)) * NN + n0 + ty * 4;
        const float4 xv = *(const float4*)&x[base];
        float4 v = make_float4(acc[0][j] + wbc + xv.x, acc[1][j] + wbc + xv.y,
                               acc[2][j] + wbc + xv.z, acc[3][j] + wbc + xv.w);
        *(float4*)&out[base] = v;
    }
}

// ---------------------------------------------------------------------------
extern "C" void kernel_launch(void* const* d_in, const int* in_sizes, int n_in,
                              void* d_out, int out_size)
{
    const float* x   = (const float*)d_in[0];
    const float* gw  = (const float*)d_in[1];
    const float* gbb = (const float*)d_in[2];
    const float* tw  = (const float*)d_in[3];
    const float* tb  = (const float*)d_in[4];
    const float* pw  = (const float*)d_in[5];
    const float* pb  = (const float*)d_in[6];
    const float* ww  = (const float*)d_in[7];
    const float* wb  = (const float*)d_in[8];
    float* out = (float*)d_out;

    proj_kernel<<<dim3(NN / 64, BB, 3), 256>>>(x, gw, gbb, tw, tb, pw, pb);
    wtrans_kernel<<<(CC * CID) / 256, 256>>>(ww);
    attn_kernel<<<dim3(NN / 64, BB), 256>>>();
    out_kernel<<<dim3(NN / 64, CC / 64, BB), 256>>>(x, wb, out);
}

// round 8
// speedup vs baseline: 3.2686x; 3.2686x over previous
#include <cuda_runtime.h>
#include <cstdint>

#define BB   8
#define CC   256
#define CID  64
#define NN   4096
#define LOG2E 1.4426950408889634f

// Scratch (no allocations allowed)
__device__ float d_theta[BB * NN * CID];  // [b][n][k], pre-scaled by log2(e)
__device__ float d_phi  [BB * NN * CID];  // [b][n][k]
__device__ float d_gm   [BB * NN * CID];  // [b][n][k]
__device__ float d_y    [BB * NN * CID];  // [b][n][k]
__device__ float d_wT   [CID * CC];       // [k][c]

__device__ __forceinline__ float ex2f(float x) {
    float y; asm("ex2.approx.f32 %0, %1;" : "=f"(y) : "f"(x)); return y;
}
__device__ __forceinline__ uint32_t smem_to_u32(const void* p) {
    uint32_t a;
    asm("{ .reg .u64 t; cvta.to.shared.u64 t, %1; cvt.u32.u64 %0, t; }"
        : "=r"(a) : "l"(p));
    return a;
}
__device__ __forceinline__ void cp_async16(uint32_t saddr, const void* gptr) {
    asm volatile("cp.async.ca.shared.global [%0], [%1], 16;"
                 :: "r"(saddr), "l"(__cvta_generic_to_global(gptr)));
}
#define CP_COMMIT() asm volatile("cp.async.commit_group;" ::: "memory")
#define CP_WAIT(n)  asm volatile("cp.async.wait_group %0;" :: "n"(n) : "memory")

// m16n8k8 tf32 mma (raw fp32 bits as tf32 operands; HW truncates mantissa)
__device__ __forceinline__ void mma8(float* d, const uint32_t* a,
                                     uint32_t b0, uint32_t b1) {
    asm volatile(
        "mma.sync.aligned.m16n8k8.row.col.f32.tf32.tf32.f32 "
        "{%0,%1,%2,%3}, {%4,%5,%6,%7}, {%8,%9}, {%0,%1,%2,%3};\n"
        : "+f"(d[0]), "+f"(d[1]), "+f"(d[2]), "+f"(d[3])
        : "r"(a[0]), "r"(a[1]), "r"(a[2]), "r"(a[3]), "r"(b0), "r"(b1));
}

// attn smem layout (floats): rows padded to 68 for conflict-free fragments
#define ROWP  68
#define TH_F  0
#define PHI_F 8704
#define G_F   26112
#define L_F   43520
#define OP_F  PHI_F
#define ATTN_SMEM_BYTES ((43520 + 128) * 4)

// XOR swizzle for fp32 smem GEMM kernels (proj/out)
#define SWZ(r, c) ((c) ^ ((r) & 28))

#define FMA16(A, a0, a1, a2, a3, bv)                                             \
    A[0][0] += (a0) * bv.x; A[0][1] += (a0) * bv.y; A[0][2] += (a0) * bv.z; A[0][3] += (a0) * bv.w; \
    A[1][0] += (a1) * bv.x; A[1][1] += (a1) * bv.y; A[1][2] += (a1) * bv.z; A[1][3] += (a1) * bv.w; \
    A[2][0] += (a2) * bv.x; A[2][1] += (a2) * bv.y; A[2][2] += (a2) * bv.z; A[2][3] += (a2) * bv.w; \
    A[3][0] += (a3) * bv.x; A[3][1] += (a3) * bv.y; A[3][2] += (a3) * bv.z; A[3][3] += (a3) * bv.w;

// ---------------------------------------------------------------------------
// Kernel 1: 1x1-conv projections. grid (N/64, B, 3), 256 threads.
// z=0: theta*log2e, z=1: phi, z=2: g — all stored [b][n][64].
// ---------------------------------------------------------------------------
__global__ __launch_bounds__(256)
void proj_kernel(const float* __restrict__ x,
                 const float* __restrict__ gw, const float* __restrict__ gb,
                 const float* __restrict__ tw, const float* __restrict__ tb,
                 const float* __restrict__ pw, const float* __restrict__ pb)
{
    __shared__ float xs[64][64];
    __shared__ float ws[64][64];

    const int tid = threadIdx.x;
    const int tx = tid & 15, ty = tid >> 4;
    const int n0 = blockIdx.x * 64;
    const int b  = blockIdx.y;
    const int pr = blockIdx.z;
    const float* w  = (pr == 0) ? tw : (pr == 1) ? pw : gw;
    const float* bi = (pr == 0) ? tb : (pr == 1) ? pb : gb;

    float acc[4][4] = {};

    for (int kc = 0; kc < CC; kc += 64) {
        #pragma unroll
        for (int rr = 0; rr < 64; rr += 16) {
            const int r  = rr + ty;
            const int c4 = tx * 4;
            *(float4*)&xs[r][c4] =
                *(const float4*)&x[((size_t)(b * CC + kc + r)) * NN + n0 + c4];
            *(float4*)&ws[r][SWZ(r, c4)] =
                *(const float4*)&w[(size_t)r * CC + kc + c4];
        }
        __syncthreads();
        #pragma unroll 8
        for (int k = 0; k < 64; k++) {
            const float4 bv = *(const float4*)&xs[k][tx * 4];
            const float a0 = ws[ty * 4 + 0][SWZ(ty * 4 + 0, k)];
            const float a1 = ws[ty * 4 + 1][SWZ(ty * 4 + 1, k)];
            const float a2 = ws[ty * 4 + 2][SWZ(ty * 4 + 2, k)];
            const float a3 = ws[ty * 4 + 3][SWZ(ty * 4 + 3, k)];
            FMA16(acc, a0, a1, a2, a3, bv);
        }
        __syncthreads();
    }

    float* outb = (pr == 0) ? d_theta : (pr == 1) ? d_phi : d_gm;
    const float sc = (pr == 0) ? LOG2E : 1.0f;
    const float b0 = bi[ty * 4 + 0], b1 = bi[ty * 4 + 1];
    const float b2 = bi[ty * 4 + 2], b3 = bi[ty * 4 + 3];
    #pragma unroll
    for (int j = 0; j < 4; j++) {
        const int n = n0 + tx * 4 + j;
        float4 v = make_float4((acc[0][j] + b0) * sc, (acc[1][j] + b1) * sc,
                               (acc[2][j] + b2) * sc, (acc[3][j] + b3) * sc);
        *(float4*)&outb[((size_t)(b * NN + n)) * CID + ty * 4] = v;
    }
}

// ---------------------------------------------------------------------------
// Kernel 2: transpose w_w [C][CI] -> d_wT [CI][C]
// ---------------------------------------------------------------------------
__global__ __launch_bounds__(256)
void wtrans_kernel(const float* __restrict__ ww)
{
    const int idx = blockIdx.x * 256 + threadIdx.x;
    const int c = idx >> 6, k = idx & 63;
    d_wT[k * CC + c] = ww[idx];
}

// ---------------------------------------------------------------------------
// Kernel 3: tf32 mma.sync flash attention (no max subtraction; log2 domain).
// grid (N/128, B), 256 threads (8 warps: 4 row-groups x 2 col-halves).
// ---------------------------------------------------------------------------
__device__ __forceinline__ void load_tile(int b, int jt, int buf,
                                          uint32_t smem_u, int tid)
{
    const int c0 = jt * 128;
    const float* ps = &d_phi[((size_t)(b * NN + c0)) * CID];
    const float* gs = &d_gm [((size_t)(b * NN + c0)) * CID];
    const uint32_t pd = smem_u + (PHI_F + buf * 8704) * 4;
    const uint32_t gd = smem_u + (G_F  + buf * 8704) * 4;
    #pragma unroll
    for (int i = 0; i < 8; i++) {
        const int idx = i * 256 + tid;
        const int row = idx >> 4, c4 = (idx & 15) << 2;
        cp_async16(pd + (row * ROWP + c4) * 4, ps + row * 64 + c4);
        cp_async16(gd + (row * ROWP + c4) * 4, gs + row * 64 + c4);
    }
}

__global__ __launch_bounds__(256, 1)
void attn_kernel()
{
    extern __shared__ float sm[];
    const uint32_t smem_u = smem_to_u32(sm);
    const int tid  = threadIdx.x;
    const int lane = tid & 31, wid = tid >> 5;
    const int warp_m = wid & 3, warp_n = wid >> 2;
    const int rb = warp_m * 32;     // warp row base within 128
    const int cb = warp_n * 64;     // warp col base within 128-col tile
    const int b  = blockIdx.y;
    const int r0 = blockIdx.x * 128;
    const int tq = lane & 3;        // threadID_in_group
    const int gq = lane >> 2;       // groupID

    if (tid < 128) sm[L_F + tid] = 0.0f;

    // prologue: theta + tile0 (group0), tile1 (group1)
    {
        const float* tsrc = &d_theta[((size_t)(b * NN + r0)) * CID];
        #pragma unroll
        for (int i = 0; i < 8; i++) {
            const int idx = i * 256 + tid;
            const int row = idx >> 4, c4 = (idx & 15) << 2;
            cp_async16(smem_u + (TH_F + row * ROWP + c4) * 4, tsrc + row * 64 + c4);
        }
    }
    load_tile(b, 0, 0, smem_u, tid);
    CP_COMMIT();
    load_tile(b, 1, 1, smem_u, tid);
    CP_COMMIT();
    CP_WAIT(1);
    __syncthreads();

    float o[2][8][4];
    #pragma unroll
    for (int m = 0; m < 2; m++)
        #pragma unroll
        for (int nf = 0; nf < 8; nf++)
            #pragma unroll
            for (int r = 0; r < 4; r++) o[m][nf][r] = 0.0f;

    const uint32_t* th = (const uint32_t*)sm;  // TH_F == 0
    const int srcA = (lane & ~3) | (tq >> 1);
    const int srcB = srcA + 2;
    const bool odd = lane & 1;

    #pragma unroll 1
    for (int jt = 0; jt < 32; jt++) {
        const int buf = jt & 1;
        const uint32_t* phb = (const uint32_t*)&sm[PHI_F + buf * 8704];
        const uint32_t* gsb = (const uint32_t*)&sm[G_F  + buf * 8704];

        // ---- S = theta @ phi^T ----
        float s[2][8][4];
        #pragma unroll
        for (int m = 0; m < 2; m++)
            #pragma unroll
            for (int nf = 0; nf < 8; nf++)
                #pragma unroll
                for (int r = 0; r < 4; r++) s[m][nf][r] = 0.0f;

        #pragma unroll
        for (int ks = 0; ks < 8; ks++) {
            const int col = ks * 8 + tq;
            uint32_t A[2][4];
            #pragma unroll
            for (int m = 0; m < 2; m++) {
                const int row = rb + m * 16 + gq;
                A[m][0] = th[row * ROWP + col];
                A[m][1] = th[(row + 8) * ROWP + col];
                A[m][2] = th[row * ROWP + col + 4];
                A[m][3] = th[(row + 8) * ROWP + col + 4];
            }
            #pragma unroll
            for (int nf = 0; nf < 8; nf++) {
                const int nr = cb + nf * 8 + gq;
                const uint32_t b0 = phb[nr * ROWP + col];
                const uint32_t b1 = phb[nr * ROWP + col + 4];
                mma8(s[0][nf], A[0], b0, b1);
                mma8(s[1][nf], A[1], b0, b1);
            }
        }

        // ---- exp (log2 domain) + row sums ----
        float ls[2][2] = {{0.f, 0.f}, {0.f, 0.f}};
        #pragma unroll
        for (int m = 0; m < 2; m++)
            #pragma unroll
            for (int nf = 0; nf < 8; nf++) {
                s[m][nf][0] = ex2f(s[m][nf][0]);
                s[m][nf][1] = ex2f(s[m][nf][1]);
                s[m][nf][2] = ex2f(s[m][nf][2]);
                s[m][nf][3] = ex2f(s[m][nf][3]);
                ls[m][0] += s[m][nf][0] + s[m][nf][1];
                ls[m][1] += s[m][nf][2] + s[m][nf][3];
            }
        #pragma unroll
        for (int m = 0; m < 2; m++)
            #pragma unroll
            for (int h = 0; h < 2; h++) {
                float v = ls[m][h];
                v += __shfl_xor_sync(0xffffffffu, v, 1);
                v += __shfl_xor_sync(0xffffffffu, v, 2);
                if (tq == 0)
                    atomicAdd(&sm[L_F + rb + m * 16 + h * 8 + gq], v);
            }

        // ---- O += P @ g (P fragments from registers via shfl permute) ----
        #pragma unroll
        for (int ks = 0; ks < 8; ks++) {
            uint32_t A[2][4];
            #pragma unroll
            for (int m = 0; m < 2; m++) {
                float u0 = __shfl_sync(0xffffffffu, s[m][ks][0], srcA);
                float u1 = __shfl_sync(0xffffffffu, s[m][ks][1], srcA);
                float v0 = __shfl_sync(0xffffffffu, s[m][ks][0], srcB);
                float v1 = __shfl_sync(0xffffffffu, s[m][ks][1], srcB);
                A[m][0] = __float_as_uint(odd ? u1 : u0);
                A[m][2] = __float_as_uint(odd ? v1 : v0);
                u0 = __shfl_sync(0xffffffffu, s[m][ks][2], srcA);
                u1 = __shfl_sync(0xffffffffu, s[m][ks][3], srcA);
                v0 = __shfl_sync(0xffffffffu, s[m][ks][2], srcB);
                v1 = __shfl_sync(0xffffffffu, s[m][ks][3], srcB);
                A[m][1] = __float_as_uint(odd ? u1 : u0);
                A[m][3] = __float_as_uint(odd ? v1 : v0);
            }
            const int krow = cb + ks * 8 + tq;
            #pragma unroll
            for (int nf = 0; nf < 8; nf++) {
                const uint32_t b0 = gsb[krow * ROWP + nf * 8 + gq];
                const uint32_t b1 = gsb[(krow + 4) * ROWP + nf * 8 + gq];
                mma8(o[0][nf], A[0], b0, b1);
                mma8(o[1][nf], A[1], b0, b1);
            }
        }

        __syncthreads();
        if (jt + 2 < 32) { load_tile(b, jt + 2, buf, smem_u, tid); CP_COMMIT(); }
        if (jt < 30) { CP_WAIT(1); } else { CP_WAIT(0); }
        __syncthreads();
    }

    // ---- epilogue: reduce col-half partials, normalize by l, store y ----
    if (warp_n == 1) {
        #pragma unroll
        for (int m = 0; m < 2; m++) {
            const int row = rb + m * 16 + gq;
            #pragma unroll
            for (int nf = 0; nf < 8; nf++) {
                *(float2*)&sm[OP_F + row * ROWP + nf * 8 + 2 * tq] =
                    make_float2(o[m][nf][0], o[m][nf][1]);
                *(float2*)&sm[OP_F + (row + 8) * ROWP + nf * 8 + 2 * tq] =
                    make_float2(o[m][nf][2], o[m][nf][3]);
            }
        }
    }
    __syncthreads();
    if (warp_n == 0) {
        #pragma unroll
        for (int m = 0; m < 2; m++) {
            const int row = rb + m * 16 + gq;
            const float inv0 = 1.0f / sm[L_F + row];
            const float inv1 = 1.0f / sm[L_F + row + 8];
            #pragma unroll
            for (int nf = 0; nf < 8; nf++) {
                const float2 q0 = *(const float2*)&sm[OP_F + row * ROWP + nf * 8 + 2 * tq];
                const float2 q1 = *(const float2*)&sm[OP_F + (row + 8) * ROWP + nf * 8 + 2 * tq];
                float2 y0 = make_float2((o[m][nf][0] + q0.x) * inv0,
                                        (o[m][nf][1] + q0.y) * inv0);
                float2 y1 = make_float2((o[m][nf][2] + q1.x) * inv1,
                                        (o[m][nf][3] + q1.y) * inv1);
                *(float2*)&d_y[((size_t)(b * NN + r0 + row)) * CID + nf * 8 + 2 * tq] = y0;
                *(float2*)&d_y[((size_t)(b * NN + r0 + row + 8)) * CID + nf * 8 + 2 * tq] = y1;
            }
        }
    }
}

// ---------------------------------------------------------------------------
// Kernel 4: out = w_w @ y + w_b + x. grid (N/64, C/64, B), 256 threads.
// ---------------------------------------------------------------------------
__global__ __launch_bounds__(256)
void out_kernel(const float* __restrict__ x, const float* __restrict__ wb,
                float* __restrict__ out)
{
    __shared__ float y_s [64][64];
    __shared__ float wT_s[64][64];

    const int tid = threadIdx.x;
    const int tx = tid & 15, ty = tid >> 4;
    const int n0 = blockIdx.x * 64;
    const int c0 = blockIdx.y * 64;
    const int b  = blockIdx.z;

    #pragma unroll
    for (int rr = 0; rr < 64; rr += 16) {
        const int r = rr + ty, c4 = tx * 4;
        *(float4*)&y_s[r][SWZ(r, c4)] =
            *(const float4*)&d_y[((size_t)(b * NN + n0 + r)) * CID + c4];
        *(float4*)&wT_s[r][c4] = *(const float4*)&d_wT[r * CC + c0 + c4];
    }
    __syncthreads();

    float acc[4][4] = {};
    #pragma unroll 8
    for (int k = 0; k < 64; k++) {
        const float4 bv = *(const float4*)&wT_s[k][tx * 4];
        const float a0 = y_s[ty * 4 + 0][SWZ(ty * 4 + 0, k)];
        const float a1 = y_s[ty * 4 + 1][SWZ(ty * 4 + 1, k)];
        const float a2 = y_s[ty * 4 + 2][SWZ(ty * 4 + 2, k)];
        const float a3 = y_s[ty * 4 + 3][SWZ(ty * 4 + 3, k)];
        FMA16(acc, a0, a1, a2, a3, bv);
    }

    #pragma unroll
    for (int j = 0; j < 4; j++) {
        const int c = c0 + tx * 4 + j;
        const float wbc = wb[c];
        const size_t base = ((size_t)(b * CC + c)) * NN + n0 + ty * 4;
        const float4 xv = *(const float4*)&x[base];
        float4 v = make_float4(acc[0][j] + wbc + xv.x, acc[1][j] + wbc + xv.y,
                               acc[2][j] + wbc + xv.z, acc[3][j] + wbc + xv.w);
        *(float4*)&out[base] = v;
    }
}

// ---------------------------------------------------------------------------
extern "C" void kernel_launch(void* const* d_in, const int* in_sizes, int n_in,
                              void* d_out, int out_size)
{
    const float* x   = (const float*)d_in[0];
    const float* gw  = (const float*)d_in[1];
    const float* gbb = (const float*)d_in[2];
    const float* tw  = (const float*)d_in[3];
    const float* tb  = (const float*)d_in[4];
    const float* pw  = (const float*)d_in[5];
    const float* pb  = (const float*)d_in[6];
    const float* ww  = (const float*)d_in[7];
    const float* wb  = (const float*)d_in[8];
    float* out = (float*)d_out;

    cudaFuncSetAttribute(attn_kernel,
                         cudaFuncAttributeMaxDynamicSharedMemorySize,
                         ATTN_SMEM_BYTES);

    proj_kernel<<<dim3(NN / 64, BB, 3), 256>>>(x, gw, gbb, tw, tb, pw, pb);
    wtrans_kernel<<<(CC * CID) / 256, 256>>>(ww);
    attn_kernel<<<dim3(NN / 128, BB), 256, ATTN_SMEM_BYTES>>>();
    out_kernel<<<dim3(NN / 64, CC / 64, BB), 256>>>(x, wb, out);
}

// round 14
// speedup vs baseline: 4.3019x; 1.3161x over previous
#include <cuda_runtime.h>
#include <cstdint>

#define BB   8
#define CC   256
#define CID  64
#define NN   4096
#define LOG2E 1.4426950408889634f

// Scratch (no allocations allowed)
__device__ float d_theta[BB * NN * CID];  // [b][n][k], pre-scaled by log2(e)
__device__ float d_phi  [BB * NN * CID];  // [b][n][k]
__device__ float d_gm   [BB * NN * CID];  // [b][n][k]
__device__ float d_y    [BB * NN * CID];  // [b][n][k]

__device__ __forceinline__ float ex2f(float x) {
    float y; asm("ex2.approx.f32 %0, %1;" : "=f"(y) : "f"(x)); return y;
}
__device__ __forceinline__ uint32_t smem_to_u32(const void* p) {
    uint32_t a;
    asm("{ .reg .u64 t; cvta.to.shared.u64 t, %1; cvt.u32.u64 %0, t; }"
        : "=r"(a) : "l"(p));
    return a;
}
__device__ __forceinline__ void cp_async16(uint32_t saddr, const void* gptr) {
    asm volatile("cp.async.ca.shared.global [%0], [%1], 16;"
                 :: "r"(saddr), "l"(__cvta_generic_to_global(gptr)));
}
#define CP_COMMIT() asm volatile("cp.async.commit_group;" ::: "memory")
#define CP_WAIT(n)  asm volatile("cp.async.wait_group %0;" :: "n"(n) : "memory")

// m16n8k8 tf32 mma (raw fp32 bits as tf32 operands; HW truncates mantissa)
__device__ __forceinline__ void mma8(float* d, const uint32_t* a,
                                     uint32_t b0, uint32_t b1) {
    asm volatile(
        "mma.sync.aligned.m16n8k8.row.col.f32.tf32.tf32.f32 "
        "{%0,%1,%2,%3}, {%4,%5,%6,%7}, {%8,%9}, {%0,%1,%2,%3};\n"
        : "+f"(d[0]), "+f"(d[1]), "+f"(d[2]), "+f"(d[3])
        : "r"(a[0]), "r"(a[1]), "r"(a[2]), "r"(a[3]), "r"(b0), "r"(b1));
}

#define FB(x) __float_as_uint(x)

// attn smem layout (floats): rows padded to 68 for conflict-free fragments
#define ROWP  68
#define TH_F  0
#define PHI_F 8704
#define G_F   26112
#define L_F   43520
#define OP_F  PHI_F
#define ATTN_SMEM_BYTES ((43520 + 128) * 4)

// ---------------------------------------------------------------------------
// Kernel 1: tf32 MMA 1x1-conv projections. grid (N/128, B, 3), 256 threads.
// out[n][ci] = sum_c x[c][n] * w[ci][c] (+bias)(*log2e for theta)
// A = x^T fragments read from skewed [k][n] tiles; B = w (k-major native).
// ---------------------------------------------------------------------------
#define PROJ_SMEM (24576 * 4)   // x: 2x[64][128] + w: 2x[64][64] floats

__global__ __launch_bounds__(256, 2)
void proj_tc(const float* __restrict__ x,
             const float* __restrict__ gw, const float* __restrict__ gb,
             const float* __restrict__ tw, const float* __restrict__ tb,
             const float* __restrict__ pw, const float* __restrict__ pb)
{
    extern __shared__ float psm[];
    const uint32_t su = smem_to_u32(psm);
    const int tid = threadIdx.x;
    const int lane = tid & 31, wid = tid >> 5;
    const int tq = lane & 3, gq = lane >> 2;
    const int rb = (wid & 3) * 32;   // n-rows
    const int cb = (wid >> 2) * 32;  // ci-cols
    const int n0 = blockIdx.x * 128;
    const int b  = blockIdx.y;
    const int pr = blockIdx.z;
    const float* w  = (pr == 0) ? tw : (pr == 1) ? pw : gw;
    const float* bi = (pr == 0) ? tb : (pr == 1) ? pb : gb;

    // chunk loader: x chunk [64 k][128 n] skewed, w chunk [64 ci][64 k] skewed
    auto load_chunk = [&](int kc, int buf) {
        const float* xsrc = x + ((size_t)(b * CC + kc)) * NN + n0;
        const uint32_t xd = su + (buf * 8192) * 4;
        #pragma unroll
        for (int i = 0; i < 8; i++) {
            const int idx = i * 256 + tid;
            const int row = idx >> 5, c4 = (idx & 31) << 2;
            cp_async16(xd + (row * 128 + ((c4 + 4 * row) & 127)) * 4,
                       xsrc + (size_t)row * NN + c4);
        }
        const float* wsrc = w + kc;
        const uint32_t wd = su + (16384 + buf * 4096) * 4;
        #pragma unroll
        for (int i = 0; i < 4; i++) {
            const int idx = i * 256 + tid;
            const int row = idx >> 4, c4 = (idx & 15) << 2;
            cp_async16(wd + (row * 64 + ((c4 + 4 * row) & 63)) * 4,
                       wsrc + row * CC + c4);
        }
    };

    load_chunk(0, 0); CP_COMMIT();
    load_chunk(64, 1); CP_COMMIT();
    CP_WAIT(1);
    __syncthreads();

    float f[2][4][4] = {};

    #pragma unroll 1
    for (int ch = 0; ch < 4; ch++) {
        const int buf = ch & 1;
        const float* xs = psm + buf * 8192;
        const float* ws = psm + 16384 + buf * 4096;
        #pragma unroll
        for (int ks = 0; ks < 8; ks++) {
            const int col = ks * 8 + tq;
            uint32_t A[2][4];
            #pragma unroll
            for (int m = 0; m < 2; m++) {
                const int n = rb + m * 16 + gq;
                A[m][0] = FB(xs[col * 128 + ((n + 4 * col) & 127)]);
                A[m][1] = FB(xs[col * 128 + ((n + 8 + 4 * col) & 127)]);
                A[m][2] = FB(xs[(col + 4) * 128 + ((n + 4 * (col + 4)) & 127)]);
                A[m][3] = FB(xs[(col + 4) * 128 + ((n + 8 + 4 * (col + 4)) & 127)]);
            }
            #pragma unroll
            for (int nf = 0; nf < 4; nf++) {
                const int ci = cb + nf * 8 + gq;
                const uint32_t b0 = FB(ws[ci * 64 + ((col + 4 * ci) & 63)]);
                const uint32_t b1 = FB(ws[ci * 64 + ((col + 4 + 4 * ci) & 63)]);
                mma8(f[0][nf], A[0], b0, b1);
                mma8(f[1][nf], A[1], b0, b1);
            }
        }
        __syncthreads();
        if (ch + 2 < 4) { load_chunk((ch + 2) * 64, buf); CP_COMMIT(); CP_WAIT(1); }
        else            { CP_WAIT(0); }
        __syncthreads();
    }

    float* outb = (pr == 0) ? d_theta : (pr == 1) ? d_phi : d_gm;
    const float sc = (pr == 0) ? LOG2E : 1.0f;
    #pragma unroll
    for (int nf = 0; nf < 4; nf++) {
        const int ci0 = cb + nf * 8 + 2 * tq;
        const float bv0 = __ldg(&bi[ci0]);
        const float bv1 = __ldg(&bi[ci0 + 1]);
        #pragma unroll
        for (int m = 0; m < 2; m++)
            #pragma unroll
            for (int h = 0; h < 2; h++) {
                const int row = rb + m * 16 + gq + h * 8;
                float2 v = make_float2((f[m][nf][h * 2 + 0] + bv0) * sc,
                                       (f[m][nf][h * 2 + 1] + bv1) * sc);
                *(float2*)&outb[((size_t)(b * NN + n0 + row)) * CID + ci0] = v;
            }
    }
}

// ---------------------------------------------------------------------------
// Kernel 2: tf32 mma.sync flash attention (no max subtraction; log2 domain).
// grid (N/128, B), 256 threads (8 warps: 4 row-groups x 2 col-halves).
// [UNCHANGED from the 426us passing kernel]
// ---------------------------------------------------------------------------
__device__ __forceinline__ void load_tile(int b, int jt, int buf,
                                          uint32_t smem_u, int tid)
{
    const int c0 = jt * 128;
    const float* ps = &d_phi[((size_t)(b * NN + c0)) * CID];
    const float* gs = &d_gm [((size_t)(b * NN + c0)) * CID];
    const uint32_t pd = smem_u + (PHI_F + buf * 8704) * 4;
    const uint32_t gd = smem_u + (G_F  + buf * 8704) * 4;
    #pragma unroll
    for (int i = 0; i < 8; i++) {
        const int idx = i * 256 + tid;
        const int row = idx >> 4, c4 = (idx & 15) << 2;
        cp_async16(pd + (row * ROWP + c4) * 4, ps + row * 64 + c4);
        cp_async16(gd + (row * ROWP + c4) * 4, gs + row * 64 + c4);
    }
}

__global__ __launch_bounds__(256, 1)
void attn_kernel()
{
    extern __shared__ float sm[];
    const uint32_t smem_u = smem_to_u32(sm);
    const int tid  = threadIdx.x;
    const int lane = tid & 31, wid = tid >> 5;
    const int warp_m = wid & 3, warp_n = wid >> 2;
    const int rb = warp_m * 32;     // warp row base within 128
    const int cb = warp_n * 64;     // warp col base within 128-col tile
    const int b  = blockIdx.y;
    const int r0 = blockIdx.x * 128;
    const int tq = lane & 3;        // threadID_in_group
    const int gq = lane >> 2;       // groupID

    if (tid < 128) sm[L_F + tid] = 0.0f;

    // prologue: theta + tile0, tile1
    {
        const float* tsrc = &d_theta[((size_t)(b * NN + r0)) * CID];
        #pragma unroll
        for (int i = 0; i < 8; i++) {
            const int idx = i * 256 + tid;
            const int row = idx >> 4, c4 = (idx & 15) << 2;
            cp_async16(smem_u + (TH_F + row * ROWP + c4) * 4, tsrc + row * 64 + c4);
        }
    }
    load_tile(b, 0, 0, smem_u, tid);
    CP_COMMIT();
    load_tile(b, 1, 1, smem_u, tid);
    CP_COMMIT();
    CP_WAIT(1);
    __syncthreads();

    float o[2][8][4];
    #pragma unroll
    for (int m = 0; m < 2; m++)
        #pragma unroll
        for (int nf = 0; nf < 8; nf++)
            #pragma unroll
            for (int r = 0; r < 4; r++) o[m][nf][r] = 0.0f;

    const uint32_t* th = (const uint32_t*)sm;  // TH_F == 0
    const int srcA = (lane & ~3) | (tq >> 1);
    const int srcB = srcA + 2;
    const bool odd = lane & 1;

    #pragma unroll 1
    for (int jt = 0; jt < 32; jt++) {
        const int buf = jt & 1;
        const uint32_t* phb = (const uint32_t*)&sm[PHI_F + buf * 8704];
        const uint32_t* gsb = (const uint32_t*)&sm[G_F  + buf * 8704];

        // ---- S = theta @ phi^T ----
        float s[2][8][4];
        #pragma unroll
        for (int m = 0; m < 2; m++)
            #pragma unroll
            for (int nf = 0; nf < 8; nf++)
                #pragma unroll
                for (int r = 0; r < 4; r++) s[m][nf][r] = 0.0f;

        #pragma unroll
        for (int ks = 0; ks < 8; ks++) {
            const int col = ks * 8 + tq;
            uint32_t A[2][4];
            #pragma unroll
            for (int m = 0; m < 2; m++) {
                const int row = rb + m * 16 + gq;
                A[m][0] = th[row * ROWP + col];
                A[m][1] = th[(row + 8) * ROWP + col];
                A[m][2] = th[row * ROWP + col + 4];
                A[m][3] = th[(row + 8) * ROWP + col + 4];
            }
            #pragma unroll
            for (int nf = 0; nf < 8; nf++) {
                const int nr = cb + nf * 8 + gq;
                const uint32_t b0 = phb[nr * ROWP + col];
                const uint32_t b1 = phb[nr * ROWP + col + 4];
                mma8(s[0][nf], A[0], b0, b1);
                mma8(s[1][nf], A[1], b0, b1);
            }
        }

        // ---- exp (log2 domain) + row sums ----
        float ls[2][2] = {{0.f, 0.f}, {0.f, 0.f}};
        #pragma unroll
        for (int m = 0; m < 2; m++)
            #pragma unroll
            for (int nf = 0; nf < 8; nf++) {
                s[m][nf][0] = ex2f(s[m][nf][0]);
                s[m][nf][1] = ex2f(s[m][nf][1]);
                s[m][nf][2] = ex2f(s[m][nf][2]);
                s[m][nf][3] = ex2f(s[m][nf][3]);
                ls[m][0] += s[m][nf][0] + s[m][nf][1];
                ls[m][1] += s[m][nf][2] + s[m][nf][3];
            }
        #pragma unroll
        for (int m = 0; m < 2; m++)
            #pragma unroll
            for (int h = 0; h < 2; h++) {
                float v = ls[m][h];
                v += __shfl_xor_sync(0xffffffffu, v, 1);
                v += __shfl_xor_sync(0xffffffffu, v, 2);
                if (tq == 0)
                    atomicAdd(&sm[L_F + rb + m * 16 + h * 8 + gq], v);
            }

        // ---- O += P @ g (P fragments from registers via shfl permute) ----
        #pragma unroll
        for (int ks = 0; ks < 8; ks++) {
            uint32_t A[2][4];
            #pragma unroll
            for (int m = 0; m < 2; m++) {
                float u0 = __shfl_sync(0xffffffffu, s[m][ks][0], srcA);
                float u1 = __shfl_sync(0xffffffffu, s[m][ks][1], srcA);
                float v0 = __shfl_sync(0xffffffffu, s[m][ks][0], srcB);
                float v1 = __shfl_sync(0xffffffffu, s[m][ks][1], srcB);
                A[m][0] = __float_as_uint(odd ? u1 : u0);
                A[m][2] = __float_as_uint(odd ? v1 : v0);
                u0 = __shfl_sync(0xffffffffu, s[m][ks][2], srcA);
                u1 = __shfl_sync(0xffffffffu, s[m][ks][3], srcA);
                v0 = __shfl_sync(0xffffffffu, s[m][ks][2], srcB);
                v1 = __shfl_sync(0xffffffffu, s[m][ks][3], srcB);
                A[m][1] = __float_as_uint(odd ? u1 : u0);
                A[m][3] = __float_as_uint(odd ? v1 : v0);
            }
            const int krow = cb + ks * 8 + tq;
            #pragma unroll
            for (int nf = 0; nf < 8; nf++) {
                const uint32_t b0 = gsb[krow * ROWP + nf * 8 + gq];
                const uint32_t b1 = gsb[(krow + 4) * ROWP + nf * 8 + gq];
                mma8(o[0][nf], A[0], b0, b1);
                mma8(o[1][nf], A[1], b0, b1);
            }
        }

        __syncthreads();
        if (jt + 2 < 32) { load_tile(b, jt + 2, buf, smem_u, tid); CP_COMMIT(); }
        if (jt < 30) { CP_WAIT(1); } else { CP_WAIT(0); }
        __syncthreads();
    }

    // ---- epilogue: reduce col-half partials, normalize by l, store y ----
    if (warp_n == 1) {
        #pragma unroll
        for (int m = 0; m < 2; m++) {
            const int row = rb + m * 16 + gq;
            #pragma unroll
            for (int nf = 0; nf < 8; nf++) {
                *(float2*)&sm[OP_F + row * ROWP + nf * 8 + 2 * tq] =
                    make_float2(o[m][nf][0], o[m][nf][1]);
                *(float2*)&sm[OP_F + (row + 8) * ROWP + nf * 8 + 2 * tq] =
                    make_float2(o[m][nf][2], o[m][nf][3]);
            }
        }
    }
    __syncthreads();
    if (warp_n == 0) {
        #pragma unroll
        for (int m = 0; m < 2; m++) {
            const int row = rb + m * 16 + gq;
            const float inv0 = 1.0f / sm[L_F + row];
            const float inv1 = 1.0f / sm[L_F + row + 8];
            #pragma unroll
            for (int nf = 0; nf < 8; nf++) {
                const float2 q0 = *(const float2*)&sm[OP_F + row * ROWP + nf * 8 + 2 * tq];
                const float2 q1 = *(const float2*)&sm[OP_F + (row + 8) * ROWP + nf * 8 + 2 * tq];
                float2 y0 = make_float2((o[m][nf][0] + q0.x) * inv0,
                                        (o[m][nf][1] + q0.y) * inv0);
                float2 y1 = make_float2((o[m][nf][2] + q1.x) * inv1,
                                        (o[m][nf][3] + q1.y) * inv1);
                *(float2*)&d_y[((size_t)(b * NN + r0 + row)) * CID + nf * 8 + 2 * tq] = y0;
                *(float2*)&d_y[((size_t)(b * NN + r0 + row + 8)) * CID + nf * 8 + 2 * tq] = y1;
            }
        }
    }
}

// ---------------------------------------------------------------------------
// Kernel 3: tf32 MMA output proj + residual. grid (N/64, B), 256 threads.
// out[c][n] = sum_ci w_w[c][ci]*y[n][ci] + wb[c] + x[c][n]
// Both operands natively k-major: A = w_w [256][64], B = y [n][64].
// ---------------------------------------------------------------------------
#define OUT_SMEM ((16384 + 4096) * 4)  // w [256][64] + y [64][64] floats

__global__ __launch_bounds__(256, 2)
void out_tc(const float* __restrict__ x, const float* __restrict__ ww,
            const float* __restrict__ wb, float* __restrict__ out)
{
    extern __shared__ float osm[];
    const uint32_t su = smem_to_u32(osm);
    const int tid = threadIdx.x;
    const int lane = tid & 31, wid = tid >> 5;
    const int tq = lane & 3, gq = lane >> 2;
    const int rb = (wid & 3) * 64;   // c-rows (4 m-frags each)
    const int cb = (wid >> 2) * 32;  // n-cols (4 n-frags each)
    const int n0 = blockIdx.x * 64;
    const int b  = blockIdx.y;

    // load w [256][64] skewed
    #pragma unroll
    for (int i = 0; i < 16; i++) {
        const int idx = i * 256 + tid;
        const int row = idx >> 4, c4 = (idx & 15) << 2;
        cp_async16(su + (row * 64 + ((c4 + 4 * row) & 63)) * 4,
                   ww + row * CID + c4);
    }
    // load y tile [64][64] skewed
    #pragma unroll
    for (int i = 0; i < 4; i++) {
        const int idx = i * 256 + tid;
        const int row = idx >> 4, c4 = (idx & 15) << 2;
        cp_async16(su + (16384 + row * 64 + ((c4 + 4 * row) & 63)) * 4,
                   &d_y[((size_t)(b * NN + n0 + row)) * CID + c4]);
    }
    CP_COMMIT(); CP_WAIT(0);
    __syncthreads();

    const float* ws = osm;
    const float* ys = osm + 16384;
    float acc[4][4][4] = {};

    #pragma unroll
    for (int ks = 0; ks < 8; ks++) {
        const int col = ks * 8 + tq;
        uint32_t A[4][4];
        #pragma unroll
        for (int mf = 0; mf < 4; mf++) {
            const int c = rb + mf * 16 + gq;
            A[mf][0] = FB(ws[c * 64 + ((col + 4 * c) & 63)]);
            A[mf][1] = FB(ws[(c + 8) * 64 + ((col + 4 * (c + 8)) & 63)]);
            A[mf][2] = FB(ws[c * 64 + ((col + 4 + 4 * c) & 63)]);
            A[mf][3] = FB(ws[(c + 8) * 64 + ((col + 4 + 4 * (c + 8)) & 63)]);
        }
        #pragma unroll
        for (int nf = 0; nf < 4; nf++) {
            const int n = cb + nf * 8 + gq;
            const uint32_t b0 = FB(ys[n * 64 + ((col + 4 * n) & 63)]);
            const uint32_t b1 = FB(ys[n * 64 + ((col + 4 + 4 * n) & 63)]);
            #pragma unroll
            for (int mf = 0; mf < 4; mf++) mma8(acc[mf][nf], A[mf], b0, b1);
        }
    }

    #pragma unroll
    for (int mf = 0; mf < 4; mf++)
        #pragma unroll
        for (int h = 0; h < 2; h++) {
            const int c = rb + mf * 16 + gq + h * 8;
            const float wbc = __ldg(&wb[c]);
            #pragma unroll
            for (int nf = 0; nf < 4; nf++) {
                const int n = n0 + cb + nf * 8 + 2 * tq;
                const size_t base = ((size_t)(b * CC + c)) * NN + n;
                const float2 xv = *(const float2*)&x[base];
                float2 v = make_float2(acc[mf][nf][h * 2 + 0] + wbc + xv.x,
                                       acc[mf][nf][h * 2 + 1] + wbc + xv.y);
                *(float2*)&out[base] = v;
            }
        }
}

// ---------------------------------------------------------------------------
extern "C" void kernel_launch(void* const* d_in, const int* in_sizes, int n_in,
                              void* d_out, int out_size)
{
    const float* x   = (const float*)d_in[0];
    const float* gw  = (const float*)d_in[1];
    const float* gbb = (const float*)d_in[2];
    const float* tw  = (const float*)d_in[3];
    const float* tb  = (const float*)d_in[4];
    const float* pw  = (const float*)d_in[5];
    const float* pb  = (const float*)d_in[6];
    const float* ww  = (const float*)d_in[7];
    const float* wb  = (const float*)d_in[8];
    float* out = (float*)d_out;

    cudaFuncSetAttribute(proj_tc, cudaFuncAttributeMaxDynamicSharedMemorySize,
                         PROJ_SMEM);
    cudaFuncSetAttribute(attn_kernel, cudaFuncAttributeMaxDynamicSharedMemorySize,
                         ATTN_SMEM_BYTES);
    cudaFuncSetAttribute(out_tc, cudaFuncAttributeMaxDynamicSharedMemorySize,
                         OUT_SMEM);

    proj_tc<<<dim3(NN / 128, BB, 3), 256, PROJ_SMEM>>>(x, gw, gbb, tw, tb, pw, pb);
    attn_kernel<<<dim3(NN / 128, BB), 256, ATTN_SMEM_BYTES>>>();
    out_tc<<<dim3(NN / 64, BB), 256, OUT_SMEM>>>(x, ww, wb, out);
}